// round 4
// baseline (speedup 1.0000x reference)
#include <cuda_runtime.h>
#include <cuda_bf16.h>
#include <cstdint>

#define BATCH 8
#define NPTS  8192
#define NQ    2048
#define NK    32
#define NF    16

// Output layout: flattened float32 concat of the 5-tuple
static const size_t QP_OFF  = 0;                                   // 8*2048*3      = 49152
static const size_t GF_OFF  = 49152;                               // 8*2048*32*19  = 9961472
static const size_t IDX_OFF = 49152 + 9961472;                     // 10,010,624
static const size_t GPN_OFF = IDX_OFF + (size_t)BATCH*NQ*NK;       // 10,534,912
static const size_t GP_OFF  = GPN_OFF + (size_t)BATCH*NQ*NK*3;     // 12,107,776

__device__ int g_nidx[BATCH * NQ * NK];

// ---- packed f32x2 helpers (sm_103a): per-lane IEEE .rn, identical to scalar
typedef unsigned long long u64;
__device__ __forceinline__ u64 pack2(float lo, float hi) {
    u64 r; asm("mov.b64 %0, {%1, %2};" : "=l"(r) : "f"(lo), "f"(hi)); return r;
}
__device__ __forceinline__ void unpack2(u64 v, float& lo, float& hi) {
    asm("mov.b64 {%0, %1}, %2;" : "=f"(lo), "=f"(hi) : "l"(v));
}
__device__ __forceinline__ u64 add2(u64 a, u64 b) {
    u64 r; asm("add.rn.f32x2 %0, %1, %2;" : "=l"(r) : "l"(a), "l"(b)); return r;
}
__device__ __forceinline__ u64 mul2(u64 a, u64 b) {
    u64 r; asm("mul.rn.f32x2 %0, %1, %2;" : "=l"(r) : "l"(a), "l"(b)); return r;
}

// ---------------------------------------------------------------------------
// Kernel 1: farthest point sampling. One CTA per batch, 1024 threads,
// 8 points/thread in registers as packed f32x2 pairs.
// Exact semantics: d = ((dx*dx)+(dy*dy))+(dz*dz), each op .rn (no FMA),
// dist = min(dist, d), argmax with first-index tie-break.
//
// Atomic-free reduction, ONE barrier/iter:
//   per-warp: REDUX.max + ballot elects lowest winning lane; that lane
//   resolves its first-j candidate and writes (max, coords) to slot [warp].
//   barrier. Every warp then redundantly reduces the 32 slots (conflict-free
//   LDS + REDUX + ballot -> lowest winning warp) and broadcast-loads the
//   winning float4. Lowest warp/lane/j ordering == jnp.argmax first-index.
//   Double-buffered slots make one barrier per iteration race-free.
// ---------------------------------------------------------------------------
__global__ void __launch_bounds__(1024, 1)
fps_kernel(const float* __restrict__ pts, float* __restrict__ out_qp)
{
    const int b    = blockIdx.x;
    const int t    = threadIdx.x;
    const int warp = t >> 5;
    const int lane = t & 31;
    const float* p = pts + (size_t)b * NPTS * 3;

    __shared__ float4   swc[2][32];
    __shared__ unsigned swd[2][32];

    u64 PX[4], PY[4], PZ[4];
    float dist[8];
#pragma unroll
    for (int pr = 0; pr < 4; pr++) {
        int i0 = t * 8 + pr * 2;
        float x0 = p[i0 * 3 + 0], y0 = p[i0 * 3 + 1], z0 = p[i0 * 3 + 2];
        float x1 = p[i0 * 3 + 3], y1 = p[i0 * 3 + 4], z1 = p[i0 * 3 + 5];
        PX[pr] = pack2(x0, x1); PY[pr] = pack2(y0, y1); PZ[pr] = pack2(z0, z1);
        dist[pr * 2] = 1e10f; dist[pr * 2 + 1] = 1e10f;
    }
    // initial centroid = point 0; every thread reads it (L1 broadcast)
    float4 c = make_float4(__ldg(p + 0), __ldg(p + 1), __ldg(p + 2), 0.0f);
    if (t == 0) {
        float* o = out_qp + (size_t)b * NQ * 3;
        o[0] = c.x; o[1] = c.y; o[2] = c.z;
    }

    for (int it = 1; it < NQ; ++it) {
        const int buf = it & 1;
        const u64 nx2 = pack2(-c.x, -c.x);
        const u64 ny2 = pack2(-c.y, -c.y);
        const u64 nz2 = pack2(-c.z, -c.z);

        float tmax = 0.0f;
#pragma unroll
        for (int pr = 0; pr < 4; pr++) {
            u64 dx2 = add2(PX[pr], nx2);
            u64 dy2 = add2(PY[pr], ny2);
            u64 dz2 = add2(PZ[pr], nz2);
            u64 d2  = add2(add2(mul2(dx2, dx2), mul2(dy2, dy2)), mul2(dz2, dz2));
            float d0, d1; unpack2(d2, d0, d1);
            float n0 = fminf(dist[pr * 2 + 0], d0);
            float n1 = fminf(dist[pr * 2 + 1], d1);
            dist[pr * 2 + 0] = n0; dist[pr * 2 + 1] = n1;
            tmax = fmaxf(tmax, n0);
            tmax = fmaxf(tmax, n1);
        }

        // per-warp election: lowest lane holding the warp max
        const unsigned ut = __float_as_uint(tmax);
        const unsigned wm = __reduce_max_sync(0xffffffffu, ut);
        const unsigned mk = __ballot_sync(0xffffffffu, ut == wm);
        const int wlane = __ffs(mk) - 1;
        if (lane == wlane) {
            // resolve first-j candidate in-register
            int j = 0;
#pragma unroll
            for (int jj = 7; jj >= 0; jj--)
                if (__float_as_uint(dist[jj]) == wm) j = jj;
            const int pr = j >> 1;
            u64 vx = PX[0], vy = PY[0], vz = PZ[0];
#pragma unroll
            for (int q = 1; q < 4; q++)
                if (pr == q) { vx = PX[q]; vy = PY[q]; vz = PZ[q]; }
            float lo, hi, x, y, z;
            unpack2(vx, lo, hi); x = (j & 1) ? hi : lo;
            unpack2(vy, lo, hi); y = (j & 1) ? hi : lo;
            unpack2(vz, lo, hi); z = (j & 1) ? hi : lo;
            swc[buf][warp] = make_float4(x, y, z, 0.0f);
            swd[buf][warp] = wm;
        }
        __syncthreads();

        // every warp redundantly reduces the 32 per-warp slots
        const unsigned dv = swd[buf][lane];
        const unsigned gm = __reduce_max_sync(0xffffffffu, dv);
        const int win = __ffs(__ballot_sync(0xffffffffu, dv == gm)) - 1;
        c = swc[buf][win];                      // broadcast LDS.128

        if (warp == win && lane == wlane && ut == gm) {
            float* o = out_qp + ((size_t)b * NQ + it) * 3;
            o[0] = c.x; o[1] = c.y; o[2] = c.z;
        }
    }
}

// ---------------------------------------------------------------------------
// Kernel 2: ball query (warp per query, ballot + prefix-popc, early exit).
// R2 = float(double(0.1*0.1)) matches the weakly-typed JAX scalar.
// ---------------------------------------------------------------------------
__global__ void __launch_bounds__(256)
ball_kernel(const float* __restrict__ pts, const float* __restrict__ qp,
            float* __restrict__ out_idx)
{
    const int b    = blockIdx.x;
    const int qblk = blockIdx.y;
    const int warp = threadIdx.x >> 5;
    const int lane = threadIdx.x & 31;
    const float R2 = (float)(0.1 * 0.1);    // 0.00999999977648258f
    const float* p = pts + (size_t)b * NPTS * 3;

    __shared__ int s_wi[8][NK];

    for (int qq = warp; qq < 32; qq += 8) {
        const size_t gq = (size_t)b * NQ + qblk * 32 + qq;
        const float qx = qp[gq * 3 + 0];
        const float qy = qp[gq * 3 + 1];
        const float qz = qp[gq * 3 + 2];

        int cnt = 0;
        for (int c = 0; c < NPTS / 32; c++) {
            const int i = c * 32 + lane;
            float dx = qx - __ldg(p + (size_t)i * 3 + 0);
            float dy = qy - __ldg(p + (size_t)i * 3 + 1);
            float dz = qz - __ldg(p + (size_t)i * 3 + 2);
            float d  = __fadd_rn(__fadd_rn(__fmul_rn(dx, dx), __fmul_rn(dy, dy)),
                                 __fmul_rn(dz, dz));
            const bool in = (d <= R2);
            const unsigned m = __ballot_sync(0xffffffffu, in);
            if (m) {
                const int rank = __popc(m & ((1u << lane) - 1u));
                const int slot = cnt + rank;
                if (in && slot < NK) s_wi[warp][slot] = i;
                cnt += __popc(m);
                if (cnt >= NK) break;
            }
        }
        __syncwarp();
        const int cf    = cnt < NK ? cnt : NK;
        const int first = s_wi[warp][0];
        const int v     = (lane < cf) ? s_wi[warp][lane] : first;
        g_nidx[gq * NK + lane]  = v;
        out_idx[gq * NK + lane] = (float)v;
        __syncwarp();
    }
}

// ---------------------------------------------------------------------------
// Kernel 3: gather + write grouped outputs. One thread per (b,q,k).
// ---------------------------------------------------------------------------
__global__ void __launch_bounds__(256)
gather_kernel(const float* __restrict__ pts, const float* __restrict__ feat,
              const float* __restrict__ qp, float* __restrict__ out)
{
    const int gid = blockIdx.x * blockDim.x + threadIdx.x;
    if (gid >= BATCH * NQ * NK) return;
    const int q = (gid >> 5) & (NQ - 1);
    const int b = gid >> 16;

    const int idx = g_nidx[gid];
    const size_t pb = (size_t)b * NPTS + idx;
    const float px = pts[pb * 3 + 0];
    const float py = pts[pb * 3 + 1];
    const float pz = pts[pb * 3 + 2];

    const size_t gq = (size_t)b * NQ + q;
    const float nx = px - qp[gq * 3 + 0];
    const float ny = py - qp[gq * 3 + 1];
    const float nz = pz - qp[gq * 3 + 2];

    const float4* f4 = (const float4*)(feat + pb * NF);
    const float4 f0 = f4[0], f1 = f4[1], f2 = f4[2], f3 = f4[3];

    float* gf = out + GF_OFF + (size_t)gid * 19;
    gf[0]  = nx;   gf[1]  = ny;   gf[2]  = nz;
    gf[3]  = f0.x; gf[4]  = f0.y; gf[5]  = f0.z; gf[6]  = f0.w;
    gf[7]  = f1.x; gf[8]  = f1.y; gf[9]  = f1.z; gf[10] = f1.w;
    gf[11] = f2.x; gf[12] = f2.y; gf[13] = f2.z; gf[14] = f2.w;
    gf[15] = f3.x; gf[16] = f3.y; gf[17] = f3.z; gf[18] = f3.w;

    float* gpn = out + GPN_OFF + (size_t)gid * 3;
    gpn[0] = nx; gpn[1] = ny; gpn[2] = nz;

    float* gp = out + GP_OFF + (size_t)gid * 3;
    gp[0] = px; gp[1] = py; gp[2] = pz;
}

// ---------------------------------------------------------------------------
extern "C" void kernel_launch(void* const* d_in, const int* in_sizes, int n_in,
                              void* d_out, int out_size)
{
    const float* points   = (const float*)d_in[0];
    const float* features = (const float*)d_in[1];
    if (in_sizes[0] != BATCH * NPTS * 3) {
        const float* tmp = points; points = features; features = tmp;
    }
    float* out = (float*)d_out;

    fps_kernel<<<BATCH, 1024>>>(points, out + QP_OFF);
    ball_kernel<<<dim3(BATCH, 64), 256>>>(points, out + QP_OFF, out + IDX_OFF);
    gather_kernel<<<(BATCH * NQ * NK + 255) / 256, 256>>>(points, features,
                                                          out + QP_OFF, out);
}

// round 5
// speedup vs baseline: 1.3287x; 1.3287x over previous
#include <cuda_runtime.h>
#include <cuda_bf16.h>
#include <cstdint>

#define BATCH 8
#define NPTS  8192
#define NQ    2048
#define NK    32
#define NF    16

// Output layout: flattened float32 concat of the 5-tuple
static const size_t QP_OFF  = 0;                                   // 8*2048*3      = 49152
static const size_t GF_OFF  = 49152;                               // 8*2048*32*19  = 9961472
static const size_t IDX_OFF = 49152 + 9961472;                     // 10,010,624
static const size_t GPN_OFF = IDX_OFF + (size_t)BATCH*NQ*NK;       // 10,534,912
static const size_t GP_OFF  = GPN_OFF + (size_t)BATCH*NQ*NK*3;     // 12,107,776

__device__ int g_nidx[BATCH * NQ * NK];

// ---- packed f32x2 helpers (sm_103a): per-lane IEEE .rn, identical to scalar
typedef unsigned long long u64;
__device__ __forceinline__ u64 pack2(float lo, float hi) {
    u64 r; asm("mov.b64 %0, {%1, %2};" : "=l"(r) : "f"(lo), "f"(hi)); return r;
}
__device__ __forceinline__ void unpack2(u64 v, float& lo, float& hi) {
    asm("mov.b64 {%0, %1}, %2;" : "=f"(lo), "=f"(hi) : "l"(v));
}
__device__ __forceinline__ u64 add2(u64 a, u64 b) {
    u64 r; asm("add.rn.f32x2 %0, %1, %2;" : "=l"(r) : "l"(a), "l"(b)); return r;
}
__device__ __forceinline__ u64 mul2(u64 a, u64 b) {
    u64 r; asm("mul.rn.f32x2 %0, %1, %2;" : "=l"(r) : "l"(a), "l"(b)); return r;
}
__device__ __forceinline__ float fneg_exact(float x) {   // sign-bit flip (ALU)
    return __uint_as_float(__float_as_uint(x) ^ 0x80000000u);
}

// ---------------------------------------------------------------------------
// Kernel 1: farthest point sampling. One CTA per batch, 1024 threads,
// 8 points/thread in registers as packed f32x2 pairs.
// Exact semantics: d = ((dx*dx)+(dy*dy))+(dz*dz), each op .rn (no FMA),
// dist = min(dist, d), argmax with first-index tie-break.
//
// Two barriers/iter, no coordinate publish:
//   REDUX.max -> lane0 atomicMax(s_gmax32[buf]); bar1;
//   owner threads (dist bits == gmax) resolve first-j, atomicMin(s_best[buf]);
//   t0 resets spare buffers; bar2;
//   everyone reads s_best and LDG-broadcasts the centroid from pts[best]
//   (uniform address, L1-resident). t0 writes out_qp. Tie-break = min global
//   index (atomicMin over owners, within-thread ascending j) == jnp.argmax.
// ---------------------------------------------------------------------------
__global__ void __launch_bounds__(1024, 1)
fps_kernel(const float* __restrict__ pts, float* __restrict__ out_qp)
{
    const int b = blockIdx.x;
    const int t = threadIdx.x;
    const float* p = pts + (size_t)b * NPTS * 3;

    __shared__ unsigned s_gmax[2];
    __shared__ int      s_best[2];

    u64 PX[4], PY[4], PZ[4];
    float dist[8];
#pragma unroll
    for (int pr = 0; pr < 4; pr++) {
        int i0 = t * 8 + pr * 2;
        float x0 = p[i0 * 3 + 0], y0 = p[i0 * 3 + 1], z0 = p[i0 * 3 + 2];
        float x1 = p[i0 * 3 + 3], y1 = p[i0 * 3 + 4], z1 = p[i0 * 3 + 5];
        PX[pr] = pack2(x0, x1); PY[pr] = pack2(y0, y1); PZ[pr] = pack2(z0, z1);
        dist[pr * 2] = 1e10f; dist[pr * 2 + 1] = 1e10f;
    }
    // initial centroid = point 0 (L1 broadcast load by all threads)
    float cx = __ldg(p + 0), cy = __ldg(p + 1), cz = __ldg(p + 2);
    if (t == 0) {
        s_gmax[0] = 0u; s_gmax[1] = 0u;
        s_best[0] = 0x7fffffff; s_best[1] = 0x7fffffff;
        float* o = out_qp + (size_t)b * NQ * 3;
        o[0] = cx; o[1] = cy; o[2] = cz;
    }
    __syncthreads();

    for (int it = 1; it < NQ; ++it) {
        const int buf = it & 1;
        const float nx = fneg_exact(cx), ny = fneg_exact(cy), nz = fneg_exact(cz);
        const u64 nx2 = pack2(nx, nx);
        const u64 ny2 = pack2(ny, ny);
        const u64 nz2 = pack2(nz, nz);

        float tmax = 0.0f;
#pragma unroll
        for (int pr = 0; pr < 4; pr++) {
            u64 dx2 = add2(PX[pr], nx2);            // x + (-c) == x - c exactly
            u64 dy2 = add2(PY[pr], ny2);
            u64 dz2 = add2(PZ[pr], nz2);
            u64 d2  = add2(add2(mul2(dx2, dx2), mul2(dy2, dy2)), mul2(dz2, dz2));
            float d0, d1; unpack2(d2, d0, d1);
            float n0 = fminf(dist[pr * 2 + 0], d0);
            float n1 = fminf(dist[pr * 2 + 1], d1);
            dist[pr * 2 + 0] = n0; dist[pr * 2 + 1] = n1;
            tmax = fmaxf(tmax, n0);
            tmax = fmaxf(tmax, n1);
        }

        const unsigned ut = __float_as_uint(tmax);
        const unsigned wm = __reduce_max_sync(0xffffffffu, ut);
        if ((t & 31) == 0) atomicMax(&s_gmax[buf], wm);
        __syncthreads();                            // bar1: gmax final

        const unsigned g = s_gmax[buf];
        if (ut == g) {                              // owner thread(s): rare
            int j = 0;
#pragma unroll
            for (int jj = 7; jj >= 0; jj--)         // downward => first match
                if (__float_as_uint(dist[jj]) == g) j = jj;
            atomicMin(&s_best[buf], t * 8 + j);
        }
        if (t == 0) { s_gmax[buf ^ 1] = 0u; s_best[buf ^ 1] = 0x7fffffff; }
        __syncthreads();                            // bar2: best final

        const int best = s_best[buf];
        const float* pb = p + (size_t)best * 3;     // uniform -> L1 broadcast
        cx = __ldg(pb + 0); cy = __ldg(pb + 1); cz = __ldg(pb + 2);
        if (t == 0) {
            float* o = out_qp + ((size_t)b * NQ + it) * 3;
            o[0] = cx; o[1] = cy; o[2] = cz;
        }
    }
}

// ---------------------------------------------------------------------------
// Kernel 2: ball query (warp per query, ballot + prefix-popc, early exit).
// R2 = float(double(0.1*0.1)) matches the weakly-typed JAX scalar.
// ---------------------------------------------------------------------------
__global__ void __launch_bounds__(256)
ball_kernel(const float* __restrict__ pts, const float* __restrict__ qp,
            float* __restrict__ out_idx)
{
    const int b    = blockIdx.x;
    const int qblk = blockIdx.y;
    const int warp = threadIdx.x >> 5;
    const int lane = threadIdx.x & 31;
    const float R2 = (float)(0.1 * 0.1);    // 0.00999999977648258f
    const float* p = pts + (size_t)b * NPTS * 3;

    __shared__ int s_wi[8][NK];

    for (int qq = warp; qq < 32; qq += 8) {
        const size_t gq = (size_t)b * NQ + qblk * 32 + qq;
        const float qx = qp[gq * 3 + 0];
        const float qy = qp[gq * 3 + 1];
        const float qz = qp[gq * 3 + 2];

        int cnt = 0;
        for (int c = 0; c < NPTS / 32; c++) {
            const int i = c * 32 + lane;
            float dx = qx - __ldg(p + (size_t)i * 3 + 0);
            float dy = qy - __ldg(p + (size_t)i * 3 + 1);
            float dz = qz - __ldg(p + (size_t)i * 3 + 2);
            float d  = __fadd_rn(__fadd_rn(__fmul_rn(dx, dx), __fmul_rn(dy, dy)),
                                 __fmul_rn(dz, dz));
            const bool in = (d <= R2);
            const unsigned m = __ballot_sync(0xffffffffu, in);
            if (m) {
                const int rank = __popc(m & ((1u << lane) - 1u));
                const int slot = cnt + rank;
                if (in && slot < NK) s_wi[warp][slot] = i;
                cnt += __popc(m);
                if (cnt >= NK) break;
            }
        }
        __syncwarp();
        const int cf    = cnt < NK ? cnt : NK;
        const int first = s_wi[warp][0];
        const int v     = (lane < cf) ? s_wi[warp][lane] : first;
        g_nidx[gq * NK + lane]  = v;
        out_idx[gq * NK + lane] = (float)v;
        __syncwarp();
    }
}

// ---------------------------------------------------------------------------
// Kernel 3: gather + write grouped outputs. One thread per (b,q,k).
// ---------------------------------------------------------------------------
__global__ void __launch_bounds__(256)
gather_kernel(const float* __restrict__ pts, const float* __restrict__ feat,
              const float* __restrict__ qp, float* __restrict__ out)
{
    const int gid = blockIdx.x * blockDim.x + threadIdx.x;
    if (gid >= BATCH * NQ * NK) return;
    const int q = (gid >> 5) & (NQ - 1);
    const int b = gid >> 16;

    const int idx = g_nidx[gid];
    const size_t pb = (size_t)b * NPTS + idx;
    const float px = pts[pb * 3 + 0];
    const float py = pts[pb * 3 + 1];
    const float pz = pts[pb * 3 + 2];

    const size_t gq = (size_t)b * NQ + q;
    const float nx = px - qp[gq * 3 + 0];
    const float ny = py - qp[gq * 3 + 1];
    const float nz = pz - qp[gq * 3 + 2];

    const float4* f4 = (const float4*)(feat + pb * NF);
    const float4 f0 = f4[0], f1 = f4[1], f2 = f4[2], f3 = f4[3];

    float* gf = out + GF_OFF + (size_t)gid * 19;
    gf[0]  = nx;   gf[1]  = ny;   gf[2]  = nz;
    gf[3]  = f0.x; gf[4]  = f0.y; gf[5]  = f0.z; gf[6]  = f0.w;
    gf[7]  = f1.x; gf[8]  = f1.y; gf[9]  = f1.z; gf[10] = f1.w;
    gf[11] = f2.x; gf[12] = f2.y; gf[13] = f2.z; gf[14] = f2.w;
    gf[15] = f3.x; gf[16] = f3.y; gf[17] = f3.z; gf[18] = f3.w;

    float* gpn = out + GPN_OFF + (size_t)gid * 3;
    gpn[0] = nx; gpn[1] = ny; gpn[2] = nz;

    float* gp = out + GP_OFF + (size_t)gid * 3;
    gp[0] = px; gp[1] = py; gp[2] = pz;
}

// ---------------------------------------------------------------------------
extern "C" void kernel_launch(void* const* d_in, const int* in_sizes, int n_in,
                              void* d_out, int out_size)
{
    const float* points   = (const float*)d_in[0];
    const float* features = (const float*)d_in[1];
    if (in_sizes[0] != BATCH * NPTS * 3) {
        const float* tmp = points; points = features; features = tmp;
    }
    float* out = (float*)d_out;

    fps_kernel<<<BATCH, 1024>>>(points, out + QP_OFF);
    ball_kernel<<<dim3(BATCH, 64), 256>>>(points, out + QP_OFF, out + IDX_OFF);
    gather_kernel<<<(BATCH * NQ * NK + 255) / 256, 256>>>(points, features,
                                                          out + QP_OFF, out);
}